// round 1
// baseline (speedup 1.0000x reference)
#include <cuda_runtime.h>
#include <math.h>

#define NJ 24
#define NBATCH 512
#define NV 6890
#define NC 20670      // NV*3
#define KP 207
#define KT 217
#define XDIM 82

// ---------------- scratch (static __device__, allocation-free) ----------------
__device__ float g_SJ[10 * 72];        // shapedirs ^T J_regressor  [k][j*3+c]
__device__ float g_Jt[72];             // v_template^T J_regressor  [j*3+c]
__device__ float g_pf[NBATCH * KP];    // pose features
__device__ float g_Rs[NBATCH * NJ * 9];
__device__ float g_J[NBATCH * 72];
__device__ float g_A[NBATCH * NJ * 12];     // 3x4 skinning transforms
__device__ float g_vposed[NBATCH * NC];     // 42 MB scratch

// ---------------- K0: SJ / Jt (input-only contractions) ----------------
__global__ void k0_jreg(const float* __restrict__ vt, const float* __restrict__ sd,
                        const float* __restrict__ Jr) {
    int id = blockIdx.x;              // 0..71 = j*3+c
    int j = id / 3, c = id % 3;
    int tid = threadIdx.x;
    float acc[11];
#pragma unroll
    for (int s = 0; s < 11; s++) acc[s] = 0.f;
    for (int v = tid; v < NV; v += 256) {
        float w = Jr[v * NJ + j];
        acc[10] += vt[v * 3 + c] * w;
#pragma unroll
        for (int k = 0; k < 10; k++) acc[k] += sd[k * NC + v * 3 + c] * w;
    }
    __shared__ float red[256];
    for (int s = 0; s < 11; s++) {
        red[tid] = acc[s];
        __syncthreads();
        for (int off = 128; off > 0; off >>= 1) {
            if (tid < off) red[tid] += red[tid + off];
            __syncthreads();
        }
        if (tid == 0) {
            if (s < 10) g_SJ[s * 72 + id] = red[0];
            else        g_Jt[id] = red[0];
        }
        __syncthreads();
    }
}

// ---------------- K1a: Rodrigues + pose features + joint positions ----------------
__global__ void k1a_rot(const float* __restrict__ x) {
    int t = blockIdx.x * blockDim.x + threadIdx.x;
    if (t >= NBATCH * NJ) return;
    int b = t / NJ, j = t % NJ;
    const float* xb = x + b * XDIM;
    float tx = xb[j * 3 + 0], ty = xb[j * 3 + 1], tz = xb[j * 3 + 2];
    // reference: angle = ||theta + 1e-8||  (elementwise add), r = theta/angle
    float ax = tx + 1e-8f, ay = ty + 1e-8f, az = tz + 1e-8f;
    float ang = sqrtf(ax * ax + ay * ay + az * az);
    float inv = 1.f / ang;
    float rx = tx * inv, ry = ty * inv, rz = tz * inv;
    float sn, cs;
    sincosf(ang, &sn, &cs);
    float omc = 1.f - cs;
    float R[9];
    R[0] = cs + omc * rx * rx; R[1] = omc * rx * ry - sn * rz; R[2] = omc * rx * rz + sn * ry;
    R[3] = omc * rx * ry + sn * rz; R[4] = cs + omc * ry * ry; R[5] = omc * ry * rz - sn * rx;
    R[6] = omc * rx * rz - sn * ry; R[7] = omc * ry * rz + sn * rx; R[8] = cs + omc * rz * rz;
    float* rs = g_Rs + (b * NJ + j) * 9;
#pragma unroll
    for (int i = 0; i < 9; i++) rs[i] = R[i];
    if (j > 0) {
        float* pf = g_pf + b * KP + (j - 1) * 9;
#pragma unroll
        for (int i = 0; i < 9; i++)
            pf[i] = R[i] - ((i == 0 || i == 4 || i == 8) ? 1.f : 0.f);
    }
    // J[b,j,:] = Jt + betas . SJ
    float betas[10];
#pragma unroll
    for (int k = 0; k < 10; k++) betas[k] = xb[72 + k];
#pragma unroll
    for (int c = 0; c < 3; c++) {
        int jc = j * 3 + c;
        float s = g_Jt[jc];
#pragma unroll
        for (int k = 0; k < 10; k++) s += betas[k] * g_SJ[k * 72 + jc];
        g_J[b * 72 + jc] = s;
    }
}

// ---------------- K1b: kinematic chain, one warp per batch ----------------
__global__ void __launch_bounds__(128) k1b_chain(const int* __restrict__ parents) {
    int warp = threadIdx.x >> 5, lane = threadIdx.x & 31;
    int b = blockIdx.x * 4 + warp;
    __shared__ float sG[4][NJ * 12];
    float* G = sG[warp];
    const float* Rb = g_Rs + b * NJ * 9;
    const float* Jb = g_J + b * 72;
    int r = lane >> 2, cc = lane & 3;
    if (lane < 12) G[lane] = (cc < 3) ? Rb[r * 3 + cc] : Jb[r];
    __syncwarp();
    for (int i = 1; i < NJ; i++) {
        int p = parents[i];
        float val = 0.f;
        if (lane < 12) {
            const float* Gp = G + p * 12;
            if (cc < 3) {
                val = Gp[r * 4 + 0] * Rb[i * 9 + cc]
                    + Gp[r * 4 + 1] * Rb[i * 9 + 3 + cc]
                    + Gp[r * 4 + 2] * Rb[i * 9 + 6 + cc];
            } else {
                float t0 = Jb[i * 3 + 0] - Jb[p * 3 + 0];
                float t1 = Jb[i * 3 + 1] - Jb[p * 3 + 1];
                float t2 = Jb[i * 3 + 2] - Jb[p * 3 + 2];
                val = Gp[r * 4 + 0] * t0 + Gp[r * 4 + 1] * t1 + Gp[r * 4 + 2] * t2 + Gp[r * 4 + 3];
            }
        }
        __syncwarp();
        if (lane < 12) G[i * 12 + lane] = val;
        __syncwarp();
    }
    // A = G with translation column minus G_R @ J_i
    if (lane < 12) {
        for (int i = 0; i < NJ; i++) {
            float v = G[i * 12 + lane];
            if (cc == 3)
                v -= G[i * 12 + r * 4 + 0] * Jb[i * 3 + 0]
                   + G[i * 12 + r * 4 + 1] * Jb[i * 3 + 1]
                   + G[i * 12 + r * 4 + 2] * Jb[i * 3 + 2];
            g_A[b * 288 + i * 12 + lane] = v;
        }
    }
}

// ---------------- K2: fused pose+shape blend SGEMM (512 x 20670 x 217) ----------------
__global__ void __launch_bounds__(256) k2_gemm(const float* __restrict__ pd,
                                               const float* __restrict__ sd,
                                               const float* __restrict__ x,
                                               const float* __restrict__ vt) {
    __shared__ float As[8][128];
    __shared__ float Bs[8][128];
    int bn = blockIdx.x, bm = blockIdx.y;
    int tid = threadIdx.x;
    int tr = tid >> 4, tc = tid & 15;
    int n0 = bn * 128;
    float acc[8][8];
#pragma unroll
    for (int i = 0; i < 8; i++)
#pragma unroll
        for (int jj = 0; jj < 8; jj++) acc[i][jj] = 0.f;

    int aK = tid & 7;       // k within chunk
    int aM = tid >> 3;      // 0..31
    int bK = tid >> 5;      // 0..7
    int bN = tid & 31;      // 0..31

    for (int k0 = 0; k0 < KT; k0 += 8) {
#pragma unroll
        for (int q = 0; q < 4; q++) {
            int m = aM + 32 * q;
            int k = k0 + aK;
            int b = bm * 128 + m;
            float v = 0.f;
            if (k < KP)      v = g_pf[b * KP + k];
            else if (k < KT) v = x[b * XDIM + 72 + (k - KP)];
            As[aK][m] = v;
        }
#pragma unroll
        for (int q = 0; q < 4; q++) {
            int n = bN + 32 * q;
            int k = k0 + bK;
            int nn = n0 + n;
            float v = 0.f;
            if (nn < NC) {
                if (k < KP)      v = pd[k * NC + nn];
                else if (k < KT) v = sd[(k - KP) * NC + nn];
            }
            Bs[bK][n] = v;
        }
        __syncthreads();
#pragma unroll
        for (int kk = 0; kk < 8; kk++) {
            float4 a0 = *(const float4*)&As[kk][tr * 8];
            float4 a1 = *(const float4*)&As[kk][tr * 8 + 4];
            float4 b0 = *(const float4*)&Bs[kk][tc * 8];
            float4 b1 = *(const float4*)&Bs[kk][tc * 8 + 4];
            float a[8] = {a0.x, a0.y, a0.z, a0.w, a1.x, a1.y, a1.z, a1.w};
            float bb[8] = {b0.x, b0.y, b0.z, b0.w, b1.x, b1.y, b1.z, b1.w};
#pragma unroll
            for (int i = 0; i < 8; i++)
#pragma unroll
                for (int jj = 0; jj < 8; jj++) acc[i][jj] += a[i] * bb[jj];
        }
        __syncthreads();
    }
#pragma unroll
    for (int i = 0; i < 8; i++) {
        int b = bm * 128 + tr * 8 + i;
#pragma unroll
        for (int jj = 0; jj < 8; jj++) {
            int n = n0 + tc * 8 + jj;
            if (n < NC) g_vposed[(size_t)b * NC + n] = acc[i][jj] + vt[n];
        }
    }
}

// ---------------- K3: LBS skinning ----------------
__global__ void __launch_bounds__(128) k3_lbs(const float* __restrict__ Wg,
                                              float* __restrict__ out) {
    int b = blockIdx.y;
    int v0 = blockIdx.x * 384;
    int tid = threadIdx.x;
    __shared__ float sA[288];
    __shared__ float sW[384 * 25];   // padded stride 25: conflict-free
    for (int i = tid; i < 288; i += 128) sA[i] = g_A[b * 288 + i];
    for (int i = tid; i < 384 * 24; i += 128) {
        int v = i / 24, j = i % 24;
        int gv = v0 + v;
        sW[v * 25 + j] = (gv < NV) ? Wg[gv * 24 + j] : 0.f;
    }
    __syncthreads();

    float T[3][12];
#pragma unroll
    for (int t = 0; t < 3; t++)
#pragma unroll
        for (int e = 0; e < 12; e++) T[t][e] = 0.f;

#pragma unroll
    for (int j = 0; j < NJ; j++) {
        float4 a0 = *(const float4*)&sA[j * 12];
        float4 a1 = *(const float4*)&sA[j * 12 + 4];
        float4 a2 = *(const float4*)&sA[j * 12 + 8];
#pragma unroll
        for (int t = 0; t < 3; t++) {
            float w = sW[(tid + t * 128) * 25 + j];
            T[t][0] += w * a0.x; T[t][1] += w * a0.y; T[t][2] += w * a0.z; T[t][3] += w * a0.w;
            T[t][4] += w * a1.x; T[t][5] += w * a1.y; T[t][6] += w * a1.z; T[t][7] += w * a1.w;
            T[t][8] += w * a2.x; T[t][9] += w * a2.y; T[t][10] += w * a2.z; T[t][11] += w * a2.w;
        }
    }
    const float* vp = g_vposed + (size_t)b * NC;
#pragma unroll
    for (int t = 0; t < 3; t++) {
        int v = v0 + tid + t * 128;
        if (v < NV) {
            float px = vp[v * 3], py = vp[v * 3 + 1], pz = vp[v * 3 + 2];
            float* o = out + (size_t)b * NC + v * 3;
            o[0] = T[t][0] * px + T[t][1] * py + T[t][2] * pz + T[t][3];
            o[1] = T[t][4] * px + T[t][5] * py + T[t][6] * pz + T[t][7];
            o[2] = T[t][8] * px + T[t][9] * py + T[t][10] * pz + T[t][11];
        }
    }
}

// ---------------- launch ----------------
extern "C" void kernel_launch(void* const* d_in, const int* in_sizes, int n_in,
                              void* d_out, int out_size) {
    const float* x  = (const float*)d_in[0];
    const float* vt = (const float*)d_in[1];
    const float* sd = (const float*)d_in[2];
    const float* Jr = (const float*)d_in[3];
    const float* pd = (const float*)d_in[4];
    const float* Wg = (const float*)d_in[5];
    const int* parents = (const int*)d_in[6];
    float* out = (float*)d_out;

    k0_jreg<<<72, 256>>>(vt, sd, Jr);
    k1a_rot<<<48, 256>>>(x);
    k1b_chain<<<128, 128>>>(parents);
    k2_gemm<<<dim3(162, 4), 256>>>(pd, sd, x, vt);
    k3_lbs<<<dim3(18, 512), 128>>>(Wg, out);
}

// round 2
// speedup vs baseline: 1.5128x; 1.5128x over previous
#include <cuda_runtime.h>
#include <math.h>

#define NJ 24
#define NBATCH 512
#define NV 6890
#define NC 20670      // NV*3
#define KP 207
#define KT 217
#define XDIM 82

typedef unsigned long long u64;

// ---- packed f32x2 helpers (sm_103a FFMA2 path; ptxas never auto-fuses) ----
__device__ __forceinline__ u64 pack_dup(float v) {
    u64 r; unsigned u = __float_as_uint(v);
    asm("mov.b64 %0, {%1, %1};" : "=l"(r) : "r"(u));
    return r;
}
__device__ __forceinline__ void ffma2(u64& d, u64 a, u64 b) {
    asm("fma.rn.f32x2 %0, %1, %2, %3;" : "=l"(d) : "l"(a), "l"(b), "l"(d));
}
__device__ __forceinline__ u64 add2(u64 a, u64 b) {
    u64 r; asm("add.rn.f32x2 %0, %1, %2;" : "=l"(r) : "l"(a), "l"(b));
    return r;
}
__device__ __forceinline__ void unpack2(u64 p, float& x, float& y) {
    unsigned a, b;
    asm("mov.b64 {%0, %1}, %2;" : "=r"(a), "=r"(b) : "l"(p));
    x = __uint_as_float(a); y = __uint_as_float(b);
}

// ---------------- scratch (static __device__, allocation-free) ----------------
__device__ float g_SJ[10 * 72];
__device__ float g_Jt[72];
__device__ float g_pf[NBATCH * KP];
__device__ float g_Rs[NBATCH * NJ * 9];
__device__ float g_J[NBATCH * 72];
__device__ float g_A[NBATCH * NJ * 12];
__device__ float g_vposed[NBATCH * NC];

// ---------------- K0: SJ / Jt (input-only contractions) ----------------
__global__ void k0_jreg(const float* __restrict__ vt, const float* __restrict__ sd,
                        const float* __restrict__ Jr) {
    int id = blockIdx.x;
    int j = id / 3, c = id % 3;
    int tid = threadIdx.x;
    float acc[11];
#pragma unroll
    for (int s = 0; s < 11; s++) acc[s] = 0.f;
    for (int v = tid; v < NV; v += 256) {
        float w = Jr[v * NJ + j];
        acc[10] += vt[v * 3 + c] * w;
#pragma unroll
        for (int k = 0; k < 10; k++) acc[k] += sd[k * NC + v * 3 + c] * w;
    }
    __shared__ float red[256];
    for (int s = 0; s < 11; s++) {
        red[tid] = acc[s];
        __syncthreads();
        for (int off = 128; off > 0; off >>= 1) {
            if (tid < off) red[tid] += red[tid + off];
            __syncthreads();
        }
        if (tid == 0) {
            if (s < 10) g_SJ[s * 72 + id] = red[0];
            else        g_Jt[id] = red[0];
        }
        __syncthreads();
    }
}

// ---------------- K1a: Rodrigues + pose features + joint positions ----------------
__global__ void k1a_rot(const float* __restrict__ x) {
    int t = blockIdx.x * blockDim.x + threadIdx.x;
    if (t >= NBATCH * NJ) return;
    int b = t / NJ, j = t % NJ;
    const float* xb = x + b * XDIM;
    float tx = xb[j * 3 + 0], ty = xb[j * 3 + 1], tz = xb[j * 3 + 2];
    float ax = tx + 1e-8f, ay = ty + 1e-8f, az = tz + 1e-8f;
    float ang = sqrtf(ax * ax + ay * ay + az * az);
    float inv = 1.f / ang;
    float rx = tx * inv, ry = ty * inv, rz = tz * inv;
    float sn, cs;
    sincosf(ang, &sn, &cs);
    float omc = 1.f - cs;
    float R[9];
    R[0] = cs + omc * rx * rx; R[1] = omc * rx * ry - sn * rz; R[2] = omc * rx * rz + sn * ry;
    R[3] = omc * rx * ry + sn * rz; R[4] = cs + omc * ry * ry; R[5] = omc * ry * rz - sn * rx;
    R[6] = omc * rx * rz - sn * ry; R[7] = omc * ry * rz + sn * rx; R[8] = cs + omc * rz * rz;
    float* rs = g_Rs + (b * NJ + j) * 9;
#pragma unroll
    for (int i = 0; i < 9; i++) rs[i] = R[i];
    if (j > 0) {
        float* pf = g_pf + b * KP + (j - 1) * 9;
#pragma unroll
        for (int i = 0; i < 9; i++)
            pf[i] = R[i] - ((i == 0 || i == 4 || i == 8) ? 1.f : 0.f);
    }
    float betas[10];
#pragma unroll
    for (int k = 0; k < 10; k++) betas[k] = xb[72 + k];
#pragma unroll
    for (int c = 0; c < 3; c++) {
        int jc = j * 3 + c;
        float s = g_Jt[jc];
#pragma unroll
        for (int k = 0; k < 10; k++) s += betas[k] * g_SJ[k * 72 + jc];
        g_J[b * 72 + jc] = s;
    }
}

// ---------------- K1b: kinematic chain, one warp per batch ----------------
__global__ void __launch_bounds__(128) k1b_chain(const int* __restrict__ parents) {
    int warp = threadIdx.x >> 5, lane = threadIdx.x & 31;
    int b = blockIdx.x * 4 + warp;
    __shared__ float sG[4][NJ * 12];
    float* G = sG[warp];
    const float* Rb = g_Rs + b * NJ * 9;
    const float* Jb = g_J + b * 72;
    int r = lane >> 2, cc = lane & 3;
    if (lane < 12) G[lane] = (cc < 3) ? Rb[r * 3 + cc] : Jb[r];
    __syncwarp();
    for (int i = 1; i < NJ; i++) {
        int p = parents[i];
        float val = 0.f;
        if (lane < 12) {
            const float* Gp = G + p * 12;
            if (cc < 3) {
                val = Gp[r * 4 + 0] * Rb[i * 9 + cc]
                    + Gp[r * 4 + 1] * Rb[i * 9 + 3 + cc]
                    + Gp[r * 4 + 2] * Rb[i * 9 + 6 + cc];
            } else {
                float t0 = Jb[i * 3 + 0] - Jb[p * 3 + 0];
                float t1 = Jb[i * 3 + 1] - Jb[p * 3 + 1];
                float t2 = Jb[i * 3 + 2] - Jb[p * 3 + 2];
                val = Gp[r * 4 + 0] * t0 + Gp[r * 4 + 1] * t1 + Gp[r * 4 + 2] * t2 + Gp[r * 4 + 3];
            }
        }
        __syncwarp();
        if (lane < 12) G[i * 12 + lane] = val;
        __syncwarp();
    }
    if (lane < 12) {
        for (int i = 0; i < NJ; i++) {
            float v = G[i * 12 + lane];
            if (cc == 3)
                v -= G[i * 12 + r * 4 + 0] * Jb[i * 3 + 0]
                   + G[i * 12 + r * 4 + 1] * Jb[i * 3 + 1]
                   + G[i * 12 + r * 4 + 2] * Jb[i * 3 + 2];
            g_A[b * 288 + i * 12 + lane] = v;
        }
    }
}

// ---------------- K2: fused blend SGEMM, double-buffered + f32x2 ----------------
// C[512, 20670] = [pf | betas](512x217) @ [posedirs ; shapedirs](217x20670) + vt
__global__ void __launch_bounds__(256) k2_gemm(const float* __restrict__ pd,
                                               const float* __restrict__ sd,
                                               const float* __restrict__ x,
                                               const float* __restrict__ vt) {
    __shared__ __align__(16) float As[2][8][128];
    __shared__ __align__(16) float Bs[2][8][128];
    int bn = blockIdx.x, bm = blockIdx.y;
    int tid = threadIdx.x;
    int tr = tid >> 4, tc = tid & 15;
    int n0 = bn * 128;

    u64 acc[8][4];
#pragma unroll
    for (int i = 0; i < 8; i++)
#pragma unroll
        for (int j = 0; j < 4; j++) acc[i][j] = 0ULL;

    // load-thread mapping
    int aK = tid & 7;         // k within chunk for A
    int aM = tid >> 3;        // 0..31
    int bK = tid >> 5;        // 0..7 k row for B
    int bN4 = (tid & 31) * 4; // n within tile (x4)

    float ra[4], rb[4];

    // load chunk into registers for k0
    auto loadA = [&](int k0) {
        int k = k0 + aK;
#pragma unroll
        for (int q = 0; q < 4; q++) {
            int b = bm * 128 + aM + 32 * q;
            float v = 0.f;
            if (k < KP)      v = g_pf[b * KP + k];
            else if (k < KT) v = x[b * XDIM + 72 + (k - KP)];
            ra[q] = v;
        }
    };
    auto loadB = [&](int k0) {
        int k = k0 + bK;
        int n = n0 + bN4;
        if (k < KT) {
            const float* row = (k < KP) ? (pd + (size_t)k * NC) : (sd + (size_t)(k - KP) * NC);
            if (n + 3 < NC) {
                float2 v0 = *(const float2*)(row + n);
                float2 v1 = *(const float2*)(row + n + 2);
                rb[0] = v0.x; rb[1] = v0.y; rb[2] = v1.x; rb[3] = v1.y;
            } else {
#pragma unroll
                for (int q = 0; q < 4; q++)
                    rb[q] = (n + q < NC) ? row[n + q] : 0.f;
            }
        } else {
            rb[0] = rb[1] = rb[2] = rb[3] = 0.f;
        }
    };
    auto store = [&](int buf) {
#pragma unroll
        for (int q = 0; q < 4; q++) As[buf][aK][aM + 32 * q] = ra[q];
        *(float4*)&Bs[buf][bK][bN4] = make_float4(rb[0], rb[1], rb[2], rb[3]);
    };

    const int NCHUNK = 28;    // 28*8 = 224 >= 217
    loadA(0); loadB(0); store(0);
    __syncthreads();

    int buf = 0;
    for (int ch = 0; ch < NCHUNK; ch++) {
        if (ch + 1 < NCHUNK) { loadA((ch + 1) * 8); loadB((ch + 1) * 8); }
#pragma unroll
        for (int kk = 0; kk < 8; kk++) {
            float4 a0 = *(const float4*)&As[buf][kk][tr * 8];
            float4 a1 = *(const float4*)&As[buf][kk][tr * 8 + 4];
            u64 ap[8];
            ap[0] = pack_dup(a0.x); ap[1] = pack_dup(a0.y);
            ap[2] = pack_dup(a0.z); ap[3] = pack_dup(a0.w);
            ap[4] = pack_dup(a1.x); ap[5] = pack_dup(a1.y);
            ap[6] = pack_dup(a1.z); ap[7] = pack_dup(a1.w);
            ulonglong2 bv0 = *(const ulonglong2*)&Bs[buf][kk][tc * 8];
            ulonglong2 bv1 = *(const ulonglong2*)&Bs[buf][kk][tc * 8 + 4];
#pragma unroll
            for (int i = 0; i < 8; i++) {
                ffma2(acc[i][0], ap[i], bv0.x);
                ffma2(acc[i][1], ap[i], bv0.y);
                ffma2(acc[i][2], ap[i], bv1.x);
                ffma2(acc[i][3], ap[i], bv1.y);
            }
        }
        if (ch + 1 < NCHUNK) {
            store(buf ^ 1);
            __syncthreads();
            buf ^= 1;
        }
    }

    // epilogue: add vt, store packed pairs (n even, NC even -> no straddle)
#pragma unroll
    for (int i = 0; i < 8; i++) {
        int b = bm * 128 + tr * 8 + i;
        float* orow = g_vposed + (size_t)b * NC;
#pragma unroll
        for (int j = 0; j < 4; j++) {
            int n = n0 + tc * 8 + 2 * j;
            if (n < NC) {
                u64 tv = *(const u64*)(vt + n);
                *(u64*)(orow + n) = add2(acc[i][j], tv);
            }
        }
    }
}

// ---------------- K3: LBS skinning (f32x2 accumulation) ----------------
__global__ void __launch_bounds__(128) k3_lbs(const float* __restrict__ Wg,
                                              float* __restrict__ out) {
    int b = blockIdx.y;
    int v0 = blockIdx.x * 384;
    int tid = threadIdx.x;
    __shared__ __align__(16) float sA[288];
    __shared__ float sW[384 * 25];
    for (int i = tid; i < 288; i += 128) sA[i] = g_A[b * 288 + i];
    for (int i = tid; i < 384 * 24; i += 128) {
        int v = i / 24, j = i % 24;
        int gv = v0 + v;
        sW[v * 25 + j] = (gv < NV) ? Wg[gv * 24 + j] : 0.f;
    }
    __syncthreads();

    const u64* sA2 = (const u64*)sA;   // 6 pairs per joint row

    u64 T[3][6];
#pragma unroll
    for (int t = 0; t < 3; t++)
#pragma unroll
        for (int e = 0; e < 6; e++) T[t][e] = 0ULL;

#pragma unroll
    for (int j = 0; j < NJ; j++) {
        u64 a0 = sA2[j * 6 + 0], a1 = sA2[j * 6 + 1], a2 = sA2[j * 6 + 2];
        u64 a3 = sA2[j * 6 + 3], a4 = sA2[j * 6 + 4], a5 = sA2[j * 6 + 5];
#pragma unroll
        for (int t = 0; t < 3; t++) {
            u64 wp = pack_dup(sW[(tid + t * 128) * 25 + j]);
            ffma2(T[t][0], wp, a0); ffma2(T[t][1], wp, a1); ffma2(T[t][2], wp, a2);
            ffma2(T[t][3], wp, a3); ffma2(T[t][4], wp, a4); ffma2(T[t][5], wp, a5);
        }
    }
    const float* vp = g_vposed + (size_t)b * NC;
#pragma unroll
    for (int t = 0; t < 3; t++) {
        int v = v0 + tid + t * 128;
        if (v < NV) {
            float tf[12];
#pragma unroll
            for (int e = 0; e < 6; e++) unpack2(T[t][e], tf[2 * e], tf[2 * e + 1]);
            float px = vp[v * 3], py = vp[v * 3 + 1], pz = vp[v * 3 + 2];
            float* o = out + (size_t)b * NC + v * 3;
            o[0] = tf[0] * px + tf[1] * py + tf[2] * pz + tf[3];
            o[1] = tf[4] * px + tf[5] * py + tf[6] * pz + tf[7];
            o[2] = tf[8] * px + tf[9] * py + tf[10] * pz + tf[11];
        }
    }
}

// ---------------- launch ----------------
extern "C" void kernel_launch(void* const* d_in, const int* in_sizes, int n_in,
                              void* d_out, int out_size) {
    const float* x  = (const float*)d_in[0];
    const float* vt = (const float*)d_in[1];
    const float* sd = (const float*)d_in[2];
    const float* Jr = (const float*)d_in[3];
    const float* pd = (const float*)d_in[4];
    const float* Wg = (const float*)d_in[5];
    const int* parents = (const int*)d_in[6];
    float* out = (float*)d_out;

    k0_jreg<<<72, 256>>>(vt, sd, Jr);
    k1a_rot<<<48, 256>>>(x);
    k1b_chain<<<128, 128>>>(parents);
    k2_gemm<<<dim3(162, 4), 256>>>(pd, sd, x, vt);
    k3_lbs<<<dim3(18, 512), 128>>>(Wg, out);
}

// round 5
// speedup vs baseline: 1.5353x; 1.0148x over previous
#include <cuda_runtime.h>
#include <math.h>

#define NJ 24
#define NBATCH 512
#define NV 6890
#define NC 20670      // NV*3
#define KP 207
#define KT 217
#define XDIM 82

typedef unsigned long long u64;

// ---- packed f32x2 helpers (sm_103a FFMA2 path; ptxas never auto-fuses) ----
__device__ __forceinline__ u64 pack_dup(float v) {
    u64 r; unsigned u = __float_as_uint(v);
    asm("mov.b64 %0, {%1, %1};" : "=l"(r) : "r"(u));
    return r;
}
__device__ __forceinline__ void ffma2(u64& d, u64 a, u64 b) {
    asm("fma.rn.f32x2 %0, %1, %2, %3;" : "=l"(d) : "l"(a), "l"(b), "l"(d));
}
__device__ __forceinline__ u64 add2(u64 a, u64 b) {
    u64 r; asm("add.rn.f32x2 %0, %1, %2;" : "=l"(r) : "l"(a), "l"(b));
    return r;
}
__device__ __forceinline__ void unpack2(u64 p, float& x, float& y) {
    unsigned a, b;
    asm("mov.b64 {%0, %1}, %2;" : "=r"(a), "=r"(b) : "l"(p));
    x = __uint_as_float(a); y = __uint_as_float(b);
}

// ---------------- scratch (static __device__, allocation-free) ----------------
__device__ float g_SJ[10 * 72];
__device__ float g_Jt[72];
__device__ float g_part[296 * 792];
__device__ float g_pf[NBATCH * KP];
__device__ float g_Rs[NBATCH * NJ * 9];
__device__ float g_J[NBATCH * 72];
__device__ float g_A[NBATCH * NJ * 12];
__device__ float g_vposed[NBATCH * NC];

// ---------------- K0: J-regressor contraction, coalesced + deterministic ----------------
__global__ void __launch_bounds__(128) k0_acc(const float* __restrict__ vt,
                                              const float* __restrict__ sd,
                                              const float* __restrict__ Jr) {
    int gw = (blockIdx.x * 128 + threadIdx.x) >> 5;   // 0..295
    int lane = threadIdx.x & 31;
    int v0 = gw * 24;
    float acc[33];
#pragma unroll
    for (int i = 0; i < 33; i++) acc[i] = 0.f;
    int vend = v0 + 24; if (vend > NV) vend = NV;
    for (int v = v0; v < vend; v++) {
        float w = (lane < NJ) ? Jr[v * NJ + lane] : 0.f;
#pragma unroll
        for (int s = 0; s < 10; s++) {
#pragma unroll
            for (int c = 0; c < 3; c++)
                acc[s * 3 + c] += w * sd[(size_t)s * NC + v * 3 + c];
        }
#pragma unroll
        for (int c = 0; c < 3; c++)
            acc[30 + c] += w * vt[v * 3 + c];
    }
    if (lane < NJ) {
        float* dst = g_part + gw * 792 + lane * 33;
#pragma unroll
        for (int i = 0; i < 33; i++) dst[i] = acc[i];
    }
}

__global__ void k0_red() {
    int o = threadIdx.x;             // 0..791 = j*33 + idx
    if (o >= 792) return;
    float s = 0.f;
    for (int w = 0; w < 296; w++) s += g_part[w * 792 + o];
    int j = o / 33, idx = o % 33;
    if (idx < 30) g_SJ[(idx / 3) * 72 + j * 3 + (idx % 3)] = s;
    else          g_Jt[j * 3 + (idx - 30)] = s;
}

// ---------------- K1a: Rodrigues + pose features + joint positions ----------------
__global__ void k1a_rot(const float* __restrict__ x) {
    int t = blockIdx.x * blockDim.x + threadIdx.x;
    if (t >= NBATCH * NJ) return;
    int b = t / NJ, j = t % NJ;
    const float* xb = x + b * XDIM;
    float tx = xb[j * 3 + 0], ty = xb[j * 3 + 1], tz = xb[j * 3 + 2];
    float ax = tx + 1e-8f, ay = ty + 1e-8f, az = tz + 1e-8f;
    float ang = sqrtf(ax * ax + ay * ay + az * az);
    float inv = 1.f / ang;
    float rx = tx * inv, ry = ty * inv, rz = tz * inv;
    float sn, cs;
    sincosf(ang, &sn, &cs);
    float omc = 1.f - cs;
    float R[9];
    R[0] = cs + omc * rx * rx; R[1] = omc * rx * ry - sn * rz; R[2] = omc * rx * rz + sn * ry;
    R[3] = omc * rx * ry + sn * rz; R[4] = cs + omc * ry * ry; R[5] = omc * ry * rz - sn * rx;
    R[6] = omc * rx * rz - sn * ry; R[7] = omc * ry * rz + sn * rx; R[8] = cs + omc * rz * rz;
    float* rs = g_Rs + (b * NJ + j) * 9;
#pragma unroll
    for (int i = 0; i < 9; i++) rs[i] = R[i];
    if (j > 0) {
        float* pf = g_pf + b * KP + (j - 1) * 9;
#pragma unroll
        for (int i = 0; i < 9; i++)
            pf[i] = R[i] - ((i == 0 || i == 4 || i == 8) ? 1.f : 0.f);
    }
    float betas[10];
#pragma unroll
    for (int k = 0; k < 10; k++) betas[k] = xb[72 + k];
#pragma unroll
    for (int c = 0; c < 3; c++) {
        int jc = j * 3 + c;
        float s = g_Jt[jc];
#pragma unroll
        for (int k = 0; k < 10; k++) s += betas[k] * g_SJ[k * 72 + jc];
        g_J[b * 72 + jc] = s;
    }
}

// ---------------- K1b: kinematic chain, one warp per batch ----------------
__global__ void __launch_bounds__(128) k1b_chain(const int* __restrict__ parents) {
    int warp = threadIdx.x >> 5, lane = threadIdx.x & 31;
    int b = blockIdx.x * 4 + warp;
    __shared__ float sG[4][NJ * 12];
    float* G = sG[warp];
    const float* Rb = g_Rs + b * NJ * 9;
    const float* Jb = g_J + b * 72;
    int r = lane >> 2, cc = lane & 3;
    if (lane < 12) G[lane] = (cc < 3) ? Rb[r * 3 + cc] : Jb[r];
    __syncwarp();
    for (int i = 1; i < NJ; i++) {
        int p = parents[i];
        float val = 0.f;
        if (lane < 12) {
            const float* Gp = G + p * 12;
            if (cc < 3) {
                val = Gp[r * 4 + 0] * Rb[i * 9 + cc]
                    + Gp[r * 4 + 1] * Rb[i * 9 + 3 + cc]
                    + Gp[r * 4 + 2] * Rb[i * 9 + 6 + cc];
            } else {
                float t0 = Jb[i * 3 + 0] - Jb[p * 3 + 0];
                float t1 = Jb[i * 3 + 1] - Jb[p * 3 + 1];
                float t2 = Jb[i * 3 + 2] - Jb[p * 3 + 2];
                val = Gp[r * 4 + 0] * t0 + Gp[r * 4 + 1] * t1 + Gp[r * 4 + 2] * t2 + Gp[r * 4 + 3];
            }
        }
        __syncwarp();
        if (lane < 12) G[i * 12 + lane] = val;
        __syncwarp();
    }
    if (lane < 12) {
        for (int i = 0; i < NJ; i++) {
            float v = G[i * 12 + lane];
            if (cc == 3)
                v -= G[i * 12 + r * 4 + 0] * Jb[i * 3 + 0]
                   + G[i * 12 + r * 4 + 1] * Jb[i * 3 + 1]
                   + G[i * 12 + r * 4 + 2] * Jb[i * 3 + 2];
            g_A[b * 288 + i * 12 + lane] = v;
        }
    }
}

// ---------------- K2: fused blend SGEMM, double-buffered + f32x2 ----------------
// C[512, 20670] = [pf | betas](512x217) @ [posedirs ; shapedirs](217x20670) + vt
__global__ void __launch_bounds__(256) k2_gemm(const float* __restrict__ pd,
                                               const float* __restrict__ sd,
                                               const float* __restrict__ x,
                                               const float* __restrict__ vt) {
    __shared__ __align__(16) float As[2][8][128];
    __shared__ __align__(16) float Bs[2][8][128];
    int bn = blockIdx.x, bm = blockIdx.y;
    int tid = threadIdx.x;
    int tr = tid >> 4, tc = tid & 15;
    int n0 = bn * 128;

    u64 acc[8][4];
#pragma unroll
    for (int i = 0; i < 8; i++)
#pragma unroll
        for (int j = 0; j < 4; j++) acc[i][j] = 0ULL;

    int aK = tid & 7;
    int aM = tid >> 3;
    int bK = tid >> 5;
    int bN4 = (tid & 31) * 4;

    float ra[4], rb[4];

    auto loadA = [&](int k0) {
        int k = k0 + aK;
#pragma unroll
        for (int q = 0; q < 4; q++) {
            int b = bm * 128 + aM + 32 * q;
            float v = 0.f;
            if (k < KP)      v = g_pf[b * KP + k];
            else if (k < KT) v = x[b * XDIM + 72 + (k - KP)];
            ra[q] = v;
        }
    };
    auto loadB = [&](int k0) {
        int k = k0 + bK;
        int n = n0 + bN4;
        if (k < KT) {
            const float* row = (k < KP) ? (pd + (size_t)k * NC) : (sd + (size_t)(k - KP) * NC);
            if (n + 3 < NC) {
                float2 v0 = *(const float2*)(row + n);
                float2 v1 = *(const float2*)(row + n + 2);
                rb[0] = v0.x; rb[1] = v0.y; rb[2] = v1.x; rb[3] = v1.y;
            } else {
#pragma unroll
                for (int q = 0; q < 4; q++)
                    rb[q] = (n + q < NC) ? row[n + q] : 0.f;
            }
        } else {
            rb[0] = rb[1] = rb[2] = rb[3] = 0.f;
        }
    };
    auto store = [&](int buf) {
#pragma unroll
        for (int q = 0; q < 4; q++) As[buf][aK][aM + 32 * q] = ra[q];
        *(float4*)&Bs[buf][bK][bN4] = make_float4(rb[0], rb[1], rb[2], rb[3]);
    };

    const int NCHUNK = 28;
    loadA(0); loadB(0); store(0);
    __syncthreads();

    int buf = 0;
    for (int ch = 0; ch < NCHUNK; ch++) {
        if (ch + 1 < NCHUNK) { loadA((ch + 1) * 8); loadB((ch + 1) * 8); }
#pragma unroll
        for (int kk = 0; kk < 8; kk++) {
            float4 a0 = *(const float4*)&As[buf][kk][tr * 8];
            float4 a1 = *(const float4*)&As[buf][kk][tr * 8 + 4];
            u64 ap[8];
            ap[0] = pack_dup(a0.x); ap[1] = pack_dup(a0.y);
            ap[2] = pack_dup(a0.z); ap[3] = pack_dup(a0.w);
            ap[4] = pack_dup(a1.x); ap[5] = pack_dup(a1.y);
            ap[6] = pack_dup(a1.z); ap[7] = pack_dup(a1.w);
            ulonglong2 bv0 = *(const ulonglong2*)&Bs[buf][kk][tc * 8];
            ulonglong2 bv1 = *(const ulonglong2*)&Bs[buf][kk][tc * 8 + 4];
#pragma unroll
            for (int i = 0; i < 8; i++) {
                ffma2(acc[i][0], ap[i], bv0.x);
                ffma2(acc[i][1], ap[i], bv0.y);
                ffma2(acc[i][2], ap[i], bv1.x);
                ffma2(acc[i][3], ap[i], bv1.y);
            }
        }
        if (ch + 1 < NCHUNK) {
            store(buf ^ 1);
            __syncthreads();
            buf ^= 1;
        }
    }

#pragma unroll
    for (int i = 0; i < 8; i++) {
        int b = bm * 128 + tr * 8 + i;
        float* orow = g_vposed + (size_t)b * NC;
#pragma unroll
        for (int j = 0; j < 4; j++) {
            int n = n0 + tc * 8 + 2 * j;
            if (n < NC) {
                u64 tv = *(const u64*)(vt + n);
                *(u64*)(orow + n) = add2(acc[i][j], tv);
            }
        }
    }
}

// ---------------- K3: LBS skinning, W straight from gmem (no smem stage) ----------------
__global__ void __launch_bounds__(128) k3_lbs(const float* __restrict__ Wg,
                                              float* __restrict__ out) {
    int b = blockIdx.y;
    int v0 = blockIdx.x * 384;
    int tid = threadIdx.x;
    __shared__ __align__(16) float sA[288];
    for (int i = tid; i < 288; i += 128) sA[i] = g_A[b * 288 + i];
    __syncthreads();

    const u64* sA2 = (const u64*)sA;   // 6 pairs per joint row (warp-broadcast reads)
    const float* vp = g_vposed + (size_t)b * NC;

#pragma unroll
    for (int t = 0; t < 3; t++) {
        int v = v0 + tid + t * 128;
        if (v >= NV) continue;
        // 24 weights = 6 contiguous float4 (row is 96B, 16B-aligned)
        const float4* wr = (const float4*)(Wg + (size_t)v * 24);
        float w[24];
#pragma unroll
        for (int q = 0; q < 6; q++) {
            float4 f = wr[q];
            w[q * 4 + 0] = f.x; w[q * 4 + 1] = f.y; w[q * 4 + 2] = f.z; w[q * 4 + 3] = f.w;
        }
        u64 T[6];
#pragma unroll
        for (int e = 0; e < 6; e++) T[e] = 0ULL;
#pragma unroll
        for (int j = 0; j < NJ; j++) {
            u64 wp = pack_dup(w[j]);
            ffma2(T[0], wp, sA2[j * 6 + 0]);
            ffma2(T[1], wp, sA2[j * 6 + 1]);
            ffma2(T[2], wp, sA2[j * 6 + 2]);
            ffma2(T[3], wp, sA2[j * 6 + 3]);
            ffma2(T[4], wp, sA2[j * 6 + 4]);
            ffma2(T[5], wp, sA2[j * 6 + 5]);
        }
        float tf[12];
#pragma unroll
        for (int e = 0; e < 6; e++) unpack2(T[e], tf[2 * e], tf[2 * e + 1]);
        float px = vp[v * 3], py = vp[v * 3 + 1], pz = vp[v * 3 + 2];
        float* o = out + (size_t)b * NC + v * 3;
        o[0] = tf[0] * px + tf[1] * py + tf[2] * pz + tf[3];
        o[1] = tf[4] * px + tf[5] * py + tf[6] * pz + tf[7];
        o[2] = tf[8] * px + tf[9] * py + tf[10] * pz + tf[11];
    }
}

// ---------------- launch ----------------
extern "C" void kernel_launch(void* const* d_in, const int* in_sizes, int n_in,
                              void* d_out, int out_size) {
    const float* x  = (const float*)d_in[0];
    const float* vt = (const float*)d_in[1];
    const float* sd = (const float*)d_in[2];
    const float* Jr = (const float*)d_in[3];
    const float* pd = (const float*)d_in[4];
    const float* Wg = (const float*)d_in[5];
    const int* parents = (const int*)d_in[6];
    float* out = (float*)d_out;

    k0_acc<<<74, 128>>>(vt, sd, Jr);
    k0_red<<<1, 792>>>();
    k1a_rot<<<48, 256>>>(x);
    k1b_chain<<<128, 128>>>(parents);
    k2_gemm<<<dim3(162, 4), 256>>>(pd, sd, x, vt);
    k3_lbs<<<dim3(18, 512), 128>>>(Wg, out);
}

// round 6
// speedup vs baseline: 1.7499x; 1.1398x over previous
#include <cuda_runtime.h>
#include <math.h>

#define NJ 24
#define NBATCH 512
#define NV 6890
#define NC 20670      // NV*3
#define KP 207
#define KT 217
#define XDIM 82

typedef unsigned long long u64;

// ---- packed f32x2 helpers (sm_103a FFMA2 path; ptxas never auto-fuses) ----
__device__ __forceinline__ u64 pack_dup(float v) {
    u64 r; unsigned u = __float_as_uint(v);
    asm("mov.b64 %0, {%1, %1};" : "=l"(r) : "r"(u));
    return r;
}
__device__ __forceinline__ void ffma2(u64& d, u64 a, u64 b) {
    asm("fma.rn.f32x2 %0, %1, %2, %3;" : "=l"(d) : "l"(a), "l"(b), "l"(d));
}
__device__ __forceinline__ u64 add2(u64 a, u64 b) {
    u64 r; asm("add.rn.f32x2 %0, %1, %2;" : "=l"(r) : "l"(a), "l"(b));
    return r;
}
__device__ __forceinline__ void unpack2(u64 p, float& x, float& y) {
    unsigned a, b;
    asm("mov.b64 {%0, %1}, %2;" : "=r"(a), "=r"(b) : "l"(p));
    x = __uint_as_float(a); y = __uint_as_float(b);
}

// ---------------- scratch (static __device__, allocation-free) ----------------
__device__ float g_SJ[10 * 72];
__device__ float g_Jt[72];
__device__ float g_part[296 * 792];
__device__ float g_pf[NBATCH * KP];
__device__ float g_A[NBATCH * NJ * 12];
__device__ float g_vposed[NBATCH * NC];

// ---------------- K0: J-regressor contraction, coalesced + deterministic ----------------
__global__ void __launch_bounds__(128) k0_acc(const float* __restrict__ vt,
                                              const float* __restrict__ sd,
                                              const float* __restrict__ Jr) {
    int gw = (blockIdx.x * 128 + threadIdx.x) >> 5;   // 0..295
    int lane = threadIdx.x & 31;
    int v0 = gw * 24;
    float acc[33];
#pragma unroll
    for (int i = 0; i < 33; i++) acc[i] = 0.f;
    int vend = v0 + 24; if (vend > NV) vend = NV;
    for (int v = v0; v < vend; v++) {
        float w = (lane < NJ) ? Jr[v * NJ + lane] : 0.f;
#pragma unroll
        for (int s = 0; s < 10; s++) {
#pragma unroll
            for (int c = 0; c < 3; c++)
                acc[s * 3 + c] += w * sd[(size_t)s * NC + v * 3 + c];
        }
#pragma unroll
        for (int c = 0; c < 3; c++)
            acc[30 + c] += w * vt[v * 3 + c];
    }
    if (lane < NJ) {
        float* dst = g_part + gw * 792 + lane * 33;
#pragma unroll
        for (int i = 0; i < 33; i++) dst[i] = acc[i];
    }
}

__global__ void k0_red() {
    int o = threadIdx.x;             // 0..791 = j*33 + idx
    if (o >= 792) return;
    float s = 0.f;
    for (int w = 0; w < 296; w++) s += g_part[w * 792 + o];
    int j = o / 33, idx = o % 33;
    if (idx < 30) g_SJ[(idx / 3) * 72 + j * 3 + (idx % 3)] = s;
    else          g_Jt[j * 3 + (idx - 30)] = s;
}

// ---------------- K1 fused: Rodrigues + joints + kinematic chain (all smem) ----------------
// 128 threads = 4 warps, one batch per warp, 4 batches per block.
__global__ void __launch_bounds__(128) k1_fused(const float* __restrict__ x,
                                                const int* __restrict__ parents) {
    int warp = threadIdx.x >> 5, lane = threadIdx.x & 31;
    int b = blockIdx.x * 4 + warp;

    __shared__ float sR[4][NJ * 9];
    __shared__ float sJ[4][NJ * 3];
    __shared__ float sG[4][NJ * 12];
    float* Rb = sR[warp];
    float* Jb = sJ[warp];
    float* G  = sG[warp];

    const float* xb = x + b * XDIM;

    // --- Rodrigues per joint (lane = joint) ---
    if (lane < NJ) {
        int j = lane;
        float tx = xb[j * 3 + 0], ty = xb[j * 3 + 1], tz = xb[j * 3 + 2];
        float ax = tx + 1e-8f, ay = ty + 1e-8f, az = tz + 1e-8f;
        float ang = sqrtf(ax * ax + ay * ay + az * az);
        float inv = 1.f / ang;
        float rx = tx * inv, ry = ty * inv, rz = tz * inv;
        float sn, cs;
        sincosf(ang, &sn, &cs);
        float omc = 1.f - cs;
        float R[9];
        R[0] = cs + omc * rx * rx; R[1] = omc * rx * ry - sn * rz; R[2] = omc * rx * rz + sn * ry;
        R[3] = omc * rx * ry + sn * rz; R[4] = cs + omc * ry * ry; R[5] = omc * ry * rz - sn * rx;
        R[6] = omc * rx * rz - sn * ry; R[7] = omc * ry * rz + sn * rx; R[8] = cs + omc * rz * rz;
#pragma unroll
        for (int i = 0; i < 9; i++) Rb[j * 9 + i] = R[i];
        if (j > 0) {
            float* pf = g_pf + b * KP + (j - 1) * 9;
#pragma unroll
            for (int i = 0; i < 9; i++)
                pf[i] = R[i] - ((i == 0 || i == 4 || i == 8) ? 1.f : 0.f);
        }
        // J[j] = Jt + betas . SJ
        float betas[10];
#pragma unroll
        for (int k = 0; k < 10; k++) betas[k] = xb[72 + k];
#pragma unroll
        for (int c = 0; c < 3; c++) {
            int jc = j * 3 + c;
            float s = g_Jt[jc];
#pragma unroll
            for (int k = 0; k < 10; k++) s += betas[k] * g_SJ[k * 72 + jc];
            Jb[jc] = s;
        }
    }
    __syncwarp();

    // --- kinematic chain (smem-only serial loop) ---
    int r = lane >> 2, cc = lane & 3;
    if (lane < 12) G[lane] = (cc < 3) ? Rb[r * 3 + cc] : Jb[r];
    __syncwarp();
    for (int i = 1; i < NJ; i++) {
        int p = parents[i];
        float val = 0.f;
        if (lane < 12) {
            const float* Gp = G + p * 12;
            if (cc < 3) {
                val = Gp[r * 4 + 0] * Rb[i * 9 + cc]
                    + Gp[r * 4 + 1] * Rb[i * 9 + 3 + cc]
                    + Gp[r * 4 + 2] * Rb[i * 9 + 6 + cc];
            } else {
                float t0 = Jb[i * 3 + 0] - Jb[p * 3 + 0];
                float t1 = Jb[i * 3 + 1] - Jb[p * 3 + 1];
                float t2 = Jb[i * 3 + 2] - Jb[p * 3 + 2];
                val = Gp[r * 4 + 0] * t0 + Gp[r * 4 + 1] * t1 + Gp[r * 4 + 2] * t2 + Gp[r * 4 + 3];
            }
        }
        __syncwarp();
        if (lane < 12) G[i * 12 + lane] = val;
        __syncwarp();
    }
    if (lane < 12) {
#pragma unroll
        for (int i = 0; i < NJ; i++) {
            float v = G[i * 12 + lane];
            if (cc == 3)
                v -= G[i * 12 + r * 4 + 0] * Jb[i * 3 + 0]
                   + G[i * 12 + r * 4 + 1] * Jb[i * 3 + 1]
                   + G[i * 12 + r * 4 + 2] * Jb[i * 3 + 2];
            g_A[b * 288 + i * 12 + lane] = v;
        }
    }
}

// ---------------- K2: fused blend SGEMM, double-buffered + f32x2 ----------------
// C[512, 20670] = [pf | betas](512x217) @ [posedirs ; shapedirs](217x20670) + vt
__global__ void __launch_bounds__(256) k2_gemm(const float* __restrict__ pd,
                                               const float* __restrict__ sd,
                                               const float* __restrict__ x,
                                               const float* __restrict__ vt) {
    __shared__ __align__(16) float As[2][8][128];
    __shared__ __align__(16) float Bs[2][8][128];
    int bn = blockIdx.x, bm = blockIdx.y;
    int tid = threadIdx.x;
    int tr = tid >> 4, tc = tid & 15;
    int n0 = bn * 128;

    u64 acc[8][4];
#pragma unroll
    for (int i = 0; i < 8; i++)
#pragma unroll
        for (int j = 0; j < 4; j++) acc[i][j] = 0ULL;

    int aK = tid & 7;
    int aM = tid >> 3;
    int bK = tid >> 5;
    int bN4 = (tid & 31) * 4;

    float ra[4], rb[4];

    auto loadA = [&](int k0) {
        int k = k0 + aK;
#pragma unroll
        for (int q = 0; q < 4; q++) {
            int b = bm * 128 + aM + 32 * q;
            float v = 0.f;
            if (k < KP)      v = g_pf[b * KP + k];
            else if (k < KT) v = x[b * XDIM + 72 + (k - KP)];
            ra[q] = v;
        }
    };
    auto loadB = [&](int k0) {
        int k = k0 + bK;
        int n = n0 + bN4;
        if (k < KT) {
            const float* row = (k < KP) ? (pd + (size_t)k * NC) : (sd + (size_t)(k - KP) * NC);
            if (n + 3 < NC) {
                float2 v0 = *(const float2*)(row + n);
                float2 v1 = *(const float2*)(row + n + 2);
                rb[0] = v0.x; rb[1] = v0.y; rb[2] = v1.x; rb[3] = v1.y;
            } else {
#pragma unroll
                for (int q = 0; q < 4; q++)
                    rb[q] = (n + q < NC) ? row[n + q] : 0.f;
            }
        } else {
            rb[0] = rb[1] = rb[2] = rb[3] = 0.f;
        }
    };
    auto store = [&](int buf) {
#pragma unroll
        for (int q = 0; q < 4; q++) As[buf][aK][aM + 32 * q] = ra[q];
        *(float4*)&Bs[buf][bK][bN4] = make_float4(rb[0], rb[1], rb[2], rb[3]);
    };

    const int NCHUNK = 28;
    loadA(0); loadB(0); store(0);
    __syncthreads();

    int buf = 0;
    for (int ch = 0; ch < NCHUNK; ch++) {
        if (ch + 1 < NCHUNK) { loadA((ch + 1) * 8); loadB((ch + 1) * 8); }
#pragma unroll
        for (int kk = 0; kk < 8; kk++) {
            float4 a0 = *(const float4*)&As[buf][kk][tr * 8];
            float4 a1 = *(const float4*)&As[buf][kk][tr * 8 + 4];
            u64 ap[8];
            ap[0] = pack_dup(a0.x); ap[1] = pack_dup(a0.y);
            ap[2] = pack_dup(a0.z); ap[3] = pack_dup(a0.w);
            ap[4] = pack_dup(a1.x); ap[5] = pack_dup(a1.y);
            ap[6] = pack_dup(a1.z); ap[7] = pack_dup(a1.w);
            ulonglong2 bv0 = *(const ulonglong2*)&Bs[buf][kk][tc * 8];
            ulonglong2 bv1 = *(const ulonglong2*)&Bs[buf][kk][tc * 8 + 4];
#pragma unroll
            for (int i = 0; i < 8; i++) {
                ffma2(acc[i][0], ap[i], bv0.x);
                ffma2(acc[i][1], ap[i], bv0.y);
                ffma2(acc[i][2], ap[i], bv1.x);
                ffma2(acc[i][3], ap[i], bv1.y);
            }
        }
        if (ch + 1 < NCHUNK) {
            store(buf ^ 1);
            __syncthreads();
            buf ^= 1;
        }
    }

#pragma unroll
    for (int i = 0; i < 8; i++) {
        int b = bm * 128 + tr * 8 + i;
        float* orow = g_vposed + (size_t)b * NC;
#pragma unroll
        for (int j = 0; j < 4; j++) {
            int n = n0 + tc * 8 + 2 * j;
            if (n < NC) {
                u64 tv = *(const u64*)(vt + n);
                *(u64*)(orow + n) = add2(acc[i][j], tv);
            }
        }
    }
}

// ---------------- K3: LBS skinning, j-outer (A regs reused across vertices) ----------------
__global__ void __launch_bounds__(256) k3_lbs(const float* __restrict__ Wg,
                                              float* __restrict__ out) {
    int b = blockIdx.y;
    int v0 = blockIdx.x * 512;
    int tid = threadIdx.x;
    __shared__ __align__(16) float sA[288];
    for (int i = tid; i < 288; i += 256) sA[i] = g_A[b * 288 + i];
    __syncthreads();

    const u64* sA2 = (const u64*)sA;   // 6 pairs per joint row (warp-broadcast)
    const float* vp = g_vposed + (size_t)b * NC;

    // preload weights for 2 vertices per thread
    int v[2]; bool act[2];
    float w[2][24];
#pragma unroll
    for (int t = 0; t < 2; t++) {
        v[t] = v0 + tid + t * 256;
        act[t] = v[t] < NV;
        if (act[t]) {
            const float4* wr = (const float4*)(Wg + (size_t)v[t] * 24);
#pragma unroll
            for (int q = 0; q < 6; q++) {
                float4 f = wr[q];
                w[t][q * 4 + 0] = f.x; w[t][q * 4 + 1] = f.y;
                w[t][q * 4 + 2] = f.z; w[t][q * 4 + 3] = f.w;
            }
        } else {
#pragma unroll
            for (int q = 0; q < 24; q++) w[t][q] = 0.f;
        }
    }

    u64 T[2][6];
#pragma unroll
    for (int t = 0; t < 2; t++)
#pragma unroll
        for (int e = 0; e < 6; e++) T[t][e] = 0ULL;

#pragma unroll
    for (int j = 0; j < NJ; j++) {
        u64 a0 = sA2[j * 6 + 0], a1 = sA2[j * 6 + 1], a2 = sA2[j * 6 + 2];
        u64 a3 = sA2[j * 6 + 3], a4 = sA2[j * 6 + 4], a5 = sA2[j * 6 + 5];
#pragma unroll
        for (int t = 0; t < 2; t++) {
            u64 wp = pack_dup(w[t][j]);
            ffma2(T[t][0], wp, a0); ffma2(T[t][1], wp, a1); ffma2(T[t][2], wp, a2);
            ffma2(T[t][3], wp, a3); ffma2(T[t][4], wp, a4); ffma2(T[t][5], wp, a5);
        }
    }

#pragma unroll
    for (int t = 0; t < 2; t++) {
        if (!act[t]) continue;
        float tf[12];
#pragma unroll
        for (int e = 0; e < 6; e++) unpack2(T[t][e], tf[2 * e], tf[2 * e + 1]);
        float px = vp[v[t] * 3], py = vp[v[t] * 3 + 1], pz = vp[v[t] * 3 + 2];
        float* o = out + (size_t)b * NC + v[t] * 3;
        o[0] = tf[0] * px + tf[1] * py + tf[2] * pz + tf[3];
        o[1] = tf[4] * px + tf[5] * py + tf[6] * pz + tf[7];
        o[2] = tf[8] * px + tf[9] * py + tf[10] * pz + tf[11];
    }
}

// ---------------- launch ----------------
extern "C" void kernel_launch(void* const* d_in, const int* in_sizes, int n_in,
                              void* d_out, int out_size) {
    const float* x  = (const float*)d_in[0];
    const float* vt = (const float*)d_in[1];
    const float* sd = (const float*)d_in[2];
    const float* Jr = (const float*)d_in[3];
    const float* pd = (const float*)d_in[4];
    const float* Wg = (const float*)d_in[5];
    const int* parents = (const int*)d_in[6];
    float* out = (float*)d_out;

    k0_acc<<<74, 128>>>(vt, sd, Jr);
    k0_red<<<1, 792>>>();
    k1_fused<<<128, 128>>>(x, parents);
    k2_gemm<<<dim3(162, 4), 256>>>(pd, sd, x, vt);
    k3_lbs<<<dim3(14, 512), 256>>>(Wg, out);
}